// round 17
// baseline (speedup 1.0000x reference)
#include <cuda_runtime.h>
#include <cuda_fp16.h>
#include <math.h>

#define W 160
#define H 160
#define D 160
#define PLANE (H * W)              // 25600
#define VOL (D * H * W)            // 4096000
#define INV_SZ (1.0f / 125.0f)

// xy tile geometry
#define TX 32
#define TY 32
#define HX 36
#define HY 36

// final z-reduce decomposition
#define CHUNK 16
#define NCHUNK 10
#define NCOLP (160 * 160)
#define SLIDE_THREADS (NCOLP * NCHUNK)    // 256000

// 4-field pack: p0 = (F,M) batch0, p1 = (F,M) batch1
struct __align__(8) H4 { __half2 p0, p1; };

// Scratch (__device__ globals: allocation-free rule)
__device__ H4 g_t01[VOL];       // xy-box of raw pairs
__device__ H4 g_t02[VOL];       // xy-box of g pairs
__device__ H4 g_fm[VOL];        // cached half inputs
__device__ __half2 g_t2[VOL];   // xy-box of product (batch pair)
__device__ double g_acc;

__device__ __forceinline__ float frsqrt_approx(float x) {
    float y;
    asm("rsqrt.approx.f32 %0, %1;" : "=f"(y) : "f"(x));
    return y;
}
__device__ __forceinline__ int clampi(int v, int lo, int hi) {
    return v < lo ? lo : (v > hi ? hi : v);
}
__device__ __forceinline__ H4 h4add(H4 a, H4 b) {
    H4 r; r.p0 = __hadd2(a.p0, b.p0); r.p1 = __hadd2(a.p1, b.p1); return r;
}
__device__ __forceinline__ H4 h4sub(H4 a, H4 b) {
    H4 r; r.p0 = __hsub2(a.p0, b.p0); r.p1 = __hsub2(a.p1, b.p1); return r;
}
__device__ __forceinline__ float2 f2add(float2 a, float2 b) {
    return make_float2(a.x + b.x, a.y + b.y);
}
__device__ __forceinline__ float2 f2sub(float2 a, float2 b) {
    return make_float2(a.x - b.x, a.y - b.y);
}

// fp32 4-vector accumulate of an H4
struct F4 { float2 a, b; };
__device__ __forceinline__ F4 f4zero() { return F4{{0.f, 0.f}, {0.f, 0.f}}; }
__device__ __forceinline__ F4 f4addh(F4 s, H4 v) {
    s.a = f2add(s.a, __half22float2(v.p0));
    s.b = f2add(s.b, __half22float2(v.p1));
    return s;
}

__global__ void k_zero_acc() { g_acc = 0.0; }

// ---------------------------------------------------------------------------
// Loaders: operator()(j, zp). j = voxel index at plane zp (batch-1 at j+VOL
// for raw inputs; packed H4 otherwise). z-boxes read 5 clamped taps directly.
struct LoadRaw4 {
    const float* __restrict__ f;
    const float* __restrict__ m;
    H4* __restrict__ fm;
    __device__ __forceinline__ H4 operator()(int j, int) const {
        H4 r;
        r.p0 = __floats2half2_rn(f[j], m[j]);
        r.p1 = __floats2half2_rn(f[j + VOL], m[j + VOL]);
        fm[j] = r;  // duplicate writes at halo overlaps are benign
        return r;
    }
};
struct LoadG4 {     // g = (im - u)^2, u = z-box(t01)/125 on the fly
    const H4* __restrict__ fm;
    const H4* __restrict__ t01;
    __device__ __forceinline__ H4 operator()(int j, int zp) const {
        F4 u = f4zero();
#pragma unroll
        for (int d = -2; d <= 2; d++) {
            int zz = clampi(zp + d, 0, D - 1);
            u = f4addh(u, t01[j + (zz - zp) * PLANE]);
        }
        H4 a = fm[j], r;
        float2 v0 = __half22float2(a.p0);
        float2 v1 = __half22float2(a.p1);
        float d0x = v0.x - u.a.x * INV_SZ, d0y = v0.y - u.a.y * INV_SZ;
        float d1x = v1.x - u.b.x * INV_SZ, d1y = v1.y - u.b.y * INV_SZ;
        r.p0 = __floats2half2_rn(d0x * d0x, d0y * d0y);
        r.p1 = __floats2half2_rn(d1x * d1x, d1y * d1y);
        return r;
    }
};
struct LoadP4 {     // p = n_F*n_M per batch; u,v via z-boxes of t01,t02
    const H4* __restrict__ fm;
    const H4* __restrict__ t01;
    const H4* __restrict__ t02;
    __device__ __forceinline__ __half2 operator()(int j, int zp) const {
        F4 u = f4zero(), v = f4zero();
#pragma unroll
        for (int d = -2; d <= 2; d++) {
            int zz = clampi(zp + d, 0, D - 1);
            int o = j + (zz - zp) * PLANE;
            u = f4addh(u, t01[o]);
            v = f4addh(v, t02[o]);
        }
        H4 a = fm[j];
        float2 a0 = __half22float2(a.p0);
        float2 a1 = __half22float2(a.p1);
        float pr0 = fmaxf((v.a.x * INV_SZ) * (v.a.y * INV_SZ), 1e-24f);
        float pr1 = fmaxf((v.b.x * INV_SZ) * (v.b.y * INV_SZ), 1e-24f);
        float p0 = (a0.x - u.a.x * INV_SZ) * (a0.y - u.a.y * INV_SZ) * frsqrt_approx(pr0);
        float p1 = (a1.x - u.b.x * INV_SZ) * (a1.y - u.b.y * INV_SZ) * frsqrt_approx(pr1);
        return __floats2half2_rn(p0, p1);
    }
};

// ---------------------------------------------------------------------------
// xy box of one 32x32 tile of one z-plane, 4 fields packed (R13 structure).
// grid = (5, 5, D) = 4000 blocks, block = 256.
template <class L>
__global__ void __launch_bounds__(256) k_xy_pair4(L ld, H4* __restrict__ out) {
    __shared__ H4 s_in[HY][HX + 1];
    __shared__ H4 s_yr[HX][TY + 1];

    const int gx0 = blockIdx.x * TX;
    const int gy0 = blockIdx.y * TY;
    const int zp  = blockIdx.z;
    const int zbase = zp * PLANE;
    const int tid = threadIdx.x;

    // Halo load (replicate padding via clamped coords), full block, coalesced.
    for (int i = tid; i < HY * HX; i += 256) {
        int ly = i / HX;
        int lx = i - ly * HX;
        int gy = clampi(gy0 - 2 + ly, 0, H - 1);
        int gx = clampi(gx0 - 2 + lx, 0, W - 1);
        s_in[ly][lx] = ld(zbase + gy * W + gx, zp);
    }
    __syncthreads();

    // Phase A: y-box for all 36 columns, register sliding over 4 consecutive y
    for (int g = tid; g < HX * 8; g += 256) {
        int x = g % HX;
        int y0 = (g / HX) * 4;
        H4 s = h4add(h4add(h4add(h4add(s_in[y0][x], s_in[y0 + 1][x]),
                                 s_in[y0 + 2][x]), s_in[y0 + 3][x]), s_in[y0 + 4][x]);
        s_yr[x][y0] = s;
#pragma unroll
        for (int j = 1; j < 4; j++) {
            s = h4add(s, h4sub(s_in[y0 + 4 + j][x], s_in[y0 + j - 1][x]));
            s_yr[x][y0 + j] = s;
        }
    }
    __syncthreads();

    // Phase B: x-box, 4 consecutive x per thread; warp covers 4 full rows.
    {
        int xg = tid % 8;
        int yrow = tid / 8;
        int x0 = 4 * xg;
        H4 s = h4add(h4add(h4add(h4add(s_yr[x0][yrow], s_yr[x0 + 1][yrow]),
                                 s_yr[x0 + 2][yrow]), s_yr[x0 + 3][yrow]),
                     s_yr[x0 + 4][yrow]);
        __align__(16) H4 r[4];
        r[0] = s;
#pragma unroll
        for (int j = 1; j < 4; j++) {
            s = h4add(s, h4sub(s_yr[x0 + 4 + j][yrow], s_yr[x0 + j - 1][yrow]));
            r[j] = s;
        }
        int o = zbase + (gy0 + yrow) * W + gx0 + x0;
        *reinterpret_cast<uint4*>(&out[o])     = *reinterpret_cast<uint4*>(&r[0]);
        *reinterpret_cast<uint4*>(&out[o + 2]) = *reinterpret_cast<uint4*>(&r[2]);
    }
}

// Stage-3 xy kernel: half2 (batch pair) per voxel (R13 structure).
template <class L>
__global__ void __launch_bounds__(256) k_xy_one4(L ld, __half2* __restrict__ out) {
    __shared__ __half2 s_in[HY][HX + 1];
    __shared__ __half2 s_yr[HX][TY + 1];

    const int gx0 = blockIdx.x * TX;
    const int gy0 = blockIdx.y * TY;
    const int zp  = blockIdx.z;
    const int zbase = zp * PLANE;
    const int tid = threadIdx.x;

    for (int i = tid; i < HY * HX; i += 256) {
        int ly = i / HX;
        int lx = i - ly * HX;
        int gy = clampi(gy0 - 2 + ly, 0, H - 1);
        int gx = clampi(gx0 - 2 + lx, 0, W - 1);
        s_in[ly][lx] = ld(zbase + gy * W + gx, zp);
    }
    __syncthreads();

    for (int g = tid; g < HX * 8; g += 256) {
        int x = g % HX;
        int y0 = (g / HX) * 4;
        __half2 s = __hadd2(__hadd2(__hadd2(__hadd2(s_in[y0][x], s_in[y0 + 1][x]),
                                            s_in[y0 + 2][x]), s_in[y0 + 3][x]),
                            s_in[y0 + 4][x]);
        s_yr[x][y0] = s;
#pragma unroll
        for (int j = 1; j < 4; j++) {
            s = __hadd2(s, __hsub2(s_in[y0 + 4 + j][x], s_in[y0 + j - 1][x]));
            s_yr[x][y0 + j] = s;
        }
    }
    __syncthreads();

    {
        int xg = tid % 8;
        int yrow = tid / 8;
        int x0 = 4 * xg;
        __half2 s = __hadd2(__hadd2(__hadd2(__hadd2(s_yr[x0][yrow], s_yr[x0 + 1][yrow]),
                                            s_yr[x0 + 2][yrow]), s_yr[x0 + 3][yrow]),
                            s_yr[x0 + 4][yrow]);
        __align__(16) __half2 r[4];
        r[0] = s;
#pragma unroll
        for (int j = 1; j < 4; j++) {
            s = __hadd2(s, __hsub2(s_yr[x0 + 4 + j][yrow], s_yr[x0 + j - 1][yrow]));
            r[j] = s;
        }
        int o = zbase + (gy0 + yrow) * W + gx0 + x0;
        *reinterpret_cast<uint4*>(&out[o]) = *reinterpret_cast<uint4*>(r);
    }
}

// ---------------------------------------------------------------------------
// Final z-pass + masked -sum(cross^2) reduction; both batches per thread.
__global__ void k_slide_reduce4(const __half2* __restrict__ a,
                                const float* __restrict__ mask) {
    __shared__ double sdata[256];
    int tid = blockIdx.x * blockDim.x + threadIdx.x;
    double acc = 0.0;
    if (tid < SLIDE_THREADS) {
        int c = tid % NCOLP;
        int chunk = tid / NCOLP;
        int base = c;
        int z0 = chunk * CHUNK;

        float2 s = make_float2(0.f, 0.f);
#pragma unroll
        for (int d = -2; d <= 2; d++) {
            int zz = clampi(z0 + d, 0, 159);
            s = f2add(s, __half22float2(a[base + zz * PLANE]));
        }
#pragma unroll 4
        for (int j = 0; j < CHUNK; j++) {
            int z = z0 + j;
            int i = base + z * PLANE;
            acc += (double)(s.x * s.x * mask[i]) + (double)(s.y * s.y * mask[i + VOL]);
            int zn = z + 3 > 159 ? 159 : z + 3;
            int zo = z - 2 < 0 ? 0 : z - 2;
            s = f2add(s, f2sub(__half22float2(a[base + zn * PLANE]),
                               __half22float2(a[base + zo * PLANE])));
        }
    }
    int t = threadIdx.x;
    sdata[t] = acc;
    __syncthreads();
    for (int sft = 128; sft > 0; sft >>= 1) {
        if (t < sft) sdata[t] += sdata[t + sft];
        __syncthreads();
    }
    if (t == 0) atomicAdd(&g_acc, sdata[0]);
}

__global__ void k_finish(float* __restrict__ out) {
    out[0] = (float)(-g_acc);
}

// ---------------------------------------------------------------------------
extern "C" void kernel_launch(void* const* d_in, const int* in_sizes, int n_in,
                              void* d_out, int out_size) {
    const float* f    = (const float*)d_in[0];
    const float* m    = (const float*)d_in[1];
    const float* mask = (const float*)d_in[2];
    float* out = (float*)d_out;

    H4* t01 = nullptr; cudaGetSymbolAddress((void**)&t01, g_t01);
    H4* t02 = nullptr; cudaGetSymbolAddress((void**)&t02, g_t02);
    H4* fm  = nullptr; cudaGetSymbolAddress((void**)&fm, g_fm);
    __half2* t2 = nullptr; cudaGetSymbolAddress((void**)&t2, g_t2);

    dim3 grd(W / TX, H / TY, D);        // (5, 5, 160) = 4000 blocks
    const int TB = 256;
    const int gridS = (SLIDE_THREADS + TB - 1) / TB; // 1000

    k_zero_acc<<<1, 1>>>();

    // K1: xy box of raw pairs (fills fm cache) -> t01
    k_xy_pair4<<<grd, TB>>>(LoadRaw4{f, m, fm}, t01);

    // K2: xy box of g; loader computes u = z-box(t01) on the fly -> t02
    k_xy_pair4<<<grd, TB>>>(LoadG4{fm, t01}, t02);

    // K3: xy box of p; loader computes u,v = z-box(t01), z-box(t02) -> t2
    k_xy_one4<<<grd, TB>>>(LoadP4{fm, t01, t02}, t2);

    // K4: z slide + masked reduction
    k_slide_reduce4<<<gridS, TB>>>(t2, mask);

    k_finish<<<1, 1>>>(out);
    (void)in_sizes; (void)n_in; (void)out_size;
}